// round 3
// baseline (speedup 1.0000x reference)
#include <cuda_runtime.h>
#include <cuda_bf16.h>

#define T_MAX 11

// Scratch for inter-kernel communication (no allocation allowed).
__device__ float g_w[1024];
__device__ int   g_off[1024];
__device__ int   g_cnt[1024];

// ---------------------------------------------------------------------------
// Kernel 1: per-row logits -> per-segment softmax -> probs + per-row weights.
// One CTA, 256 threads. rows <= 256, S <= rows assumed (data: rows=64, S=16).
// ---------------------------------------------------------------------------
__global__ void k_probs(const float* __restrict__ hist,
                        const float* __restrict__ Wv,
                        const float* __restrict__ bv,
                        const int*   __restrict__ slice_mask,
                        float* __restrict__ probs_out,
                        int rows, int hidden, int S)
{
    __shared__ float s_logit[256];
    __shared__ float s_e[256];
    __shared__ float s_inv[256];
    __shared__ int   s_off[256], s_cnt[256], s_seg[256];

    const int tid  = threadIdx.x;
    const int lane = tid & 31;
    const int warp = tid >> 5;

    // Phase A: warp-per-row dot(hist[r], W) + b
    for (int r = warp; r < rows; r += 8) {
        const float* hr = hist + (size_t)r * hidden;
        float acc = 0.f;
        for (int c = lane; c < hidden; c += 32)
            acc = fmaf(hr[c], Wv[c], acc);
        #pragma unroll
        for (int o = 16; o; o >>= 1)
            acc += __shfl_down_sync(0xffffffffu, acc, o);
        if (lane == 0) s_logit[r] = acc + bv[0];
    }
    __syncthreads();

    // Phase B: segment offsets (serial, S<=64 -> trivial)
    if (tid == 0) {
        int off = 0;
        for (int s = 0; s < S; s++) {
            int c = slice_mask[s];
            s_off[s] = off; s_cnt[s] = c;
            g_off[s] = off; g_cnt[s] = c;
            off += c;
        }
    }
    __syncthreads();

    if (tid < S) {
        int off = s_off[tid], c = s_cnt[tid];
        for (int j = 0; j < c; j++) s_seg[off + j] = tid;
    }
    __syncthreads();

    if (tid < rows) s_e[tid] = __expf(s_logit[tid]);
    __syncthreads();

    if (tid < S) {
        int off = s_off[tid], c = s_cnt[tid];
        float sum = 0.f;
        for (int j = 0; j < c; j++) sum += s_e[off + j];
        s_inv[tid] = 1.f / sum;
    }

    // Zero all probs slots (d_out is poisoned; invalid slots must be 0).
    for (int i = tid; i < S * T_MAX; i += blockDim.x)
        probs_out[i] = 0.f;
    __syncthreads();

    // Valid slots + per-row weights.
    if (tid < rows) {
        int   sg   = s_seg[tid];
        float w    = s_e[tid] * s_inv[sg];
        g_w[tid]   = w;
        int   pos  = tid - s_off[sg];
        int   padl = T_MAX - s_cnt[sg];
        probs_out[sg * T_MAX + padl + pos] = w;
    }
}

// ---------------------------------------------------------------------------
// Kernel 2: weighted segment-sum, float4-vectorized streaming.
//   blockIdx.y = segment s.
//   blockIdx.x < gridDim.x-1 : new_bert chunk (256 float4 per block)
//   blockIdx.x == gridDim.x-1: new_mtl (hidden/4 float4, one block)
// ---------------------------------------------------------------------------
__global__ void __launch_bounds__(256)
k_segsum(const float* __restrict__ bert,
         const float* __restrict__ mtl,
         float* __restrict__ out_bert,
         float* __restrict__ out_mtl,
         int n4_bert, int n4_mtl)
{
    const int s   = blockIdx.y;
    const int off = g_off[s];
    const int cnt = g_cnt[s];

    if ((int)blockIdx.x < (int)gridDim.x - 1) {
        int e = blockIdx.x * blockDim.x + threadIdx.x;
        if (e >= n4_bert) return;
        const float4* base = (const float4*)bert + (size_t)off * n4_bert + e;
        float4 acc = make_float4(0.f, 0.f, 0.f, 0.f);
        for (int j = 0; j < cnt; j++) {
            float  w = g_w[off + j];
            float4 v = __ldg(base + (size_t)j * n4_bert);
            acc.x = fmaf(w, v.x, acc.x);
            acc.y = fmaf(w, v.y, acc.y);
            acc.z = fmaf(w, v.z, acc.z);
            acc.w = fmaf(w, v.w, acc.w);
        }
        ((float4*)out_bert)[(size_t)s * n4_bert + e] = acc;
    } else {
        int e = threadIdx.x;
        if (e >= n4_mtl) return;
        const float4* base = (const float4*)mtl + (size_t)off * n4_mtl + e;
        float4 acc = make_float4(0.f, 0.f, 0.f, 0.f);
        for (int j = 0; j < cnt; j++) {
            float  w = g_w[off + j];
            float4 v = __ldg(base + (size_t)j * n4_mtl);
            acc.x = fmaf(w, v.x, acc.x);
            acc.y = fmaf(w, v.y, acc.y);
            acc.z = fmaf(w, v.z, acc.z);
            acc.w = fmaf(w, v.w, acc.w);
        }
        ((float4*)out_mtl)[(size_t)s * n4_mtl + e] = acc;
    }
}

// ---------------------------------------------------------------------------
// Launch. Inputs (metadata order):
//   0: bert_representation (rows, seq, hidden) f32
//   1: history_attention_input (rows, hidden)  f32
//   2: mtl_input (rows, hidden)                f32
//   3: W (1, hidden)                            f32
//   4: b (1,)                                   f32
//   5: slice_mask (rows,)                       i32
//   6: slice_num (scalar)                       i32 (unused; S derived from out_size)
// Output: [new_bert (S,seq,hidden) | new_mtl (S,hidden) | probs (S,T_MAX)] f32
// ---------------------------------------------------------------------------
extern "C" void kernel_launch(void* const* d_in, const int* in_sizes, int n_in,
                              void* d_out, int out_size)
{
    const float* bert = (const float*)d_in[0];
    const float* hist = (const float*)d_in[1];
    const float* mtl  = (const float*)d_in[2];
    const float* Wv   = (const float*)d_in[3];
    const float* bv   = (const float*)d_in[4];
    const int*   sm   = (const int*)d_in[5];

    const int hidden = in_sizes[3];                 // 768
    const int rows   = in_sizes[1] / hidden;        // 64
    const int seq    = in_sizes[0] / (rows * hidden); // 512
    const int S      = out_size / (seq * hidden + hidden + T_MAX); // 16

    float* out_bert  = (float*)d_out;
    float* out_mtl   = out_bert + (size_t)S * seq * hidden;
    float* out_probs = out_mtl  + (size_t)S * hidden;

    k_probs<<<1, 256>>>(hist, Wv, bv, sm, out_probs, rows, hidden, S);

    const int n4_bert = seq * hidden / 4;   // 98304
    const int n4_mtl  = hidden / 4;         // 192
    dim3 grid((n4_bert + 255) / 256 + 1, S);
    k_segsum<<<grid, 256>>>(bert, mtl, out_bert, out_mtl, n4_bert, n4_mtl);
}

// round 4
// speedup vs baseline: 2.5474x; 2.5474x over previous
#include <cuda_runtime.h>
#include <cuda_bf16.h>

#define T_MAX 11

// ---------------------------------------------------------------------------
// Single fused kernel.
// Grid: (GX, S). Block: 256 threads.
// Every block recomputes its segment's softmax weights (cheap, L2-resident),
// then streams its chunk of the weighted segment-sum of bert_representation.
// Block (0, s) additionally handles new_mtl row s and probs row s.
// ---------------------------------------------------------------------------
__global__ void __launch_bounds__(256)
k_fused(const float* __restrict__ bert,
        const float* __restrict__ hist,
        const float* __restrict__ mtl,
        const float* __restrict__ Wv,
        const float* __restrict__ bv,
        const int*   __restrict__ slice_mask,
        float* __restrict__ out_bert,
        float* __restrict__ out_mtl,
        float* __restrict__ out_probs,
        int hidden, int n4_bert, int n4_mtl, int S, int per_block)
{
    __shared__ int   s_mask[64];
    __shared__ float s_e[T_MAX + 5];
    __shared__ float s_w[T_MAX + 5];

    const int tid  = threadIdx.x;
    const int lane = tid & 31;
    const int warp = tid >> 5;
    const int s    = blockIdx.y;

    // ---- segment geometry ----
    if (tid < S) s_mask[tid] = slice_mask[tid];
    __syncthreads();
    int off = 0;
    #pragma unroll 4
    for (int t = 0; t < s; t++) off += s_mask[t];
    const int cnt = s_mask[s];

    // ---- per-segment logits: warp j handles rows off+j, off+j+8, ... ----
    const int nv4 = hidden >> 2;                 // 192 float4 per hist row
    for (int r = warp; r < cnt; r += 8) {
        const float4* hr = (const float4*)(hist + (size_t)(off + r) * hidden);
        const float4* wv = (const float4*)Wv;
        float acc = 0.f;
        for (int c = lane; c < nv4; c += 32) {
            float4 h = __ldg(hr + c);
            float4 w = __ldg(wv + c);
            acc = fmaf(h.x, w.x, acc);
            acc = fmaf(h.y, w.y, acc);
            acc = fmaf(h.z, w.z, acc);
            acc = fmaf(h.w, w.w, acc);
        }
        #pragma unroll
        for (int o = 16; o; o >>= 1)
            acc += __shfl_down_sync(0xffffffffu, acc, o);
        if (lane == 0) s_e[r] = __expf(acc + bv[0]);
    }
    __syncthreads();

    // ---- softmax weights (every thread; cnt <= 11) ----
    if (tid < cnt) {
        float sum = 0.f;
        for (int j = 0; j < cnt; j++) sum += s_e[j];
        s_w[tid] = s_e[tid] * (1.f / sum);
    }
    __syncthreads();

    // ---- main stream: weighted sum over cnt rows, this block's chunk ----
    const int e_base = blockIdx.x * per_block;
    const int e_end  = min(e_base + per_block, n4_bert);
    const float4* bbase = (const float4*)bert + (size_t)off * n4_bert;
    float4* obase = (float4*)out_bert + (size_t)s * n4_bert;

    #pragma unroll 4
    for (int e = e_base + tid; e < e_end; e += 256) {
        float4 acc = make_float4(0.f, 0.f, 0.f, 0.f);
        const float4* p = bbase + e;
        for (int j = 0; j < cnt; j++) {
            float  w = s_w[j];
            float4 v = __ldg(p + (size_t)j * n4_bert);
            acc.x = fmaf(w, v.x, acc.x);
            acc.y = fmaf(w, v.y, acc.y);
            acc.z = fmaf(w, v.z, acc.z);
            acc.w = fmaf(w, v.w, acc.w);
        }
        obase[e] = acc;
    }

    // ---- block (0, s): new_mtl row + probs row ----
    if (blockIdx.x == 0) {
        if (tid < n4_mtl) {
            const float4* p = (const float4*)mtl + (size_t)off * n4_mtl + tid;
            float4 acc = make_float4(0.f, 0.f, 0.f, 0.f);
            for (int j = 0; j < cnt; j++) {
                float  w = s_w[j];
                float4 v = __ldg(p + (size_t)j * n4_mtl);
                acc.x = fmaf(w, v.x, acc.x);
                acc.y = fmaf(w, v.y, acc.y);
                acc.z = fmaf(w, v.z, acc.z);
                acc.w = fmaf(w, v.w, acc.w);
            }
            ((float4*)out_mtl)[(size_t)s * n4_mtl + tid] = acc;
        }
        if (tid < T_MAX) {
            int padl = T_MAX - cnt;
            out_probs[s * T_MAX + tid] = (tid >= padl) ? s_w[tid - padl] : 0.f;
        }
    }
}

// ---------------------------------------------------------------------------
// Launch. Inputs (metadata order):
//   0: bert_representation (rows, seq, hidden) f32
//   1: history_attention_input (rows, hidden)  f32
//   2: mtl_input (rows, hidden)                f32
//   3: W (1, hidden)                            f32
//   4: b (1,)                                   f32
//   5: slice_mask (rows,)                       i32
//   6: slice_num (scalar)                       i32 (S derived from out_size)
// Output: [new_bert (S,seq,hidden) | new_mtl (S,hidden) | probs (S,T_MAX)] f32
// ---------------------------------------------------------------------------
extern "C" void kernel_launch(void* const* d_in, const int* in_sizes, int n_in,
                              void* d_out, int out_size)
{
    const float* bert = (const float*)d_in[0];
    const float* hist = (const float*)d_in[1];
    const float* mtl  = (const float*)d_in[2];
    const float* Wv   = (const float*)d_in[3];
    const float* bv   = (const float*)d_in[4];
    const int*   sm   = (const int*)d_in[5];

    const int hidden = in_sizes[3];                   // 768
    const int rows   = in_sizes[1] / hidden;          // 64
    const int seq    = in_sizes[0] / (rows * hidden); // 512
    const int S      = out_size / (seq * hidden + hidden + T_MAX); // 16

    float* out_bert  = (float*)d_out;
    float* out_mtl   = out_bert + (size_t)S * seq * hidden;
    float* out_probs = out_mtl  + (size_t)S * hidden;

    const int n4_bert = seq * hidden / 4;   // 98304
    const int n4_mtl  = hidden / 4;         // 192

    // ~2048 float4 per block -> 48 x-blocks for the reference shape.
    int GX = (n4_bert + 2047) / 2048;
    int per_block = (n4_bert + GX - 1) / GX;

    dim3 grid(GX, S);
    k_fused<<<grid, 256>>>(bert, hist, mtl, Wv, bv, sm,
                           out_bert, out_mtl, out_probs,
                           hidden, n4_bert, n4_mtl, S, per_block);
}